// round 2
// baseline (speedup 1.0000x reference)
#include <cuda_runtime.h>
#include <math.h>

// ---------------- problem constants ----------------
#define BB 2
#define CC 32
#define COC 32
#define NN 64
#define HALF 8
#define RB 16
#define NL9 9
#define K144 144
#define M4096 4096
#define HID 16

// ---------------- device scratch ----------------
__device__ float2 g_S1[BB*CC*64*64*16];   // after z-DFT  [bc][x][y*16+kz]
__device__ float2 g_S2[BB*CC*64*16*16];   // after y-DFT  [bc][x][ky*16+kz]
__device__ float2 g_XS[BB*CC*M4096];      // spectral modes [bc][(ky*16+kz)*16+kx]
__device__ float2 g_C1[BB*CC*K144];       // coeffs  [b][c][s*9+l]
__device__ float2 g_C2[BB*COC*K144];      // coeffs2 [b][o][s*9+l]
__device__ float2 g_T1[BB*COC*64*256];    // after inv x [bo][x][ky*16+kz]
__device__ float2 g_T2[BB*COC*64*64*16];  // after inv y [bo][x][y*16+kz]
__device__ int    g_shell[M4096];
__device__ float  g_YW[M4096*NL9];        // w[shell]*Y[l]
__device__ int    g_sorted[M4096];
__device__ int    g_off[17];
__device__ float2 g_TW[64];               // (cos, sin) of 2*pi*j/64

// ---------------- init: tables ----------------
__global__ void k0_init() {
    __shared__ int cnt[16];
    __shared__ int cur[16];
    __shared__ float wS[16];
    int t = threadIdx.x;
    if (t < 16) cnt[t] = 0;
    __syncthreads();
    for (int m = t; m < M4096; m += 256) {
        int ix = m >> 8, iy = (m >> 4) & 15, iz = m & 15;
        int fx = ix < 8 ? ix : ix - 16;
        int fy = iy < 8 ? iy : iy - 16;
        int fz = iz < 8 ? iz : iz - 16;
        int k2 = fx*fx + fy*fy + fz*fz;
        double r = sqrt((double)k2);
        double denom = (double)sqrtf(192.0f) + 1e-6;
        int s = (int)(r / denom * 16.0);
        if (s > 15) s = 15;
        g_shell[m] = s;
        atomicAdd(&cnt[s], 1);
        float inv = k2 > 0 ? (float)(1.0 / r) : 0.0f;
        float ux = fx * inv, uy = fy * inv, uz = fz * inv;
        float nzm = k2 > 0 ? 1.0f : 0.0f;
        float* Y = &g_YW[m * 9];
        Y[0] = 0.282095f;
        Y[1] = 0.488603f * uy;
        Y[2] = 0.488603f * uz;
        Y[3] = 0.488603f * ux;
        Y[4] = 1.092548f * ux * uy;
        Y[5] = 1.092548f * uy * uz;
        Y[6] = 0.315392f * (3.0f * uz * uz - nzm);
        Y[7] = 1.092548f * ux * uz;
        Y[8] = 0.546274f * (ux * ux - uy * uy);
    }
    __syncthreads();
    if (t < 16) wS[t] = 1.0f / sqrtf(fmaxf((float)cnt[t], 1.0f));
    if (t == 0) {
        int acc = 0;
        for (int s = 0; s < 16; s++) { g_off[s] = acc; cur[s] = acc; acc += cnt[s]; }
        g_off[16] = acc;
    }
    __syncthreads();
    for (int m = t; m < M4096; m += 256) {
        int s = g_shell[m];
        float w = wS[s];
        #pragma unroll
        for (int l = 0; l < 9; l++) g_YW[m*9+l] *= w;
        int pos = atomicAdd(&cur[s], 1);
        g_sorted[pos] = m;
    }
    if (t < 64) {
        float ang = (float)(2.0 * M_PI * (double)t / 64.0);
        g_TW[t] = make_float2(cosf(ang), sinf(ang));
    }
}

// ---------------- K1: forward z-DFT (real input), 64 -> 16 ----------------
__global__ void k1_zdft(const float* __restrict__ x) {
    __shared__ float xr[4096];
    __shared__ float2 tw[1024];
    int blk = blockIdx.x;           // (b*32+c)*64 + xcoord
    int t = threadIdx.x;
    const float* src = x + (size_t)blk * 4096;
    for (int i = t; i < 4096; i += 256) xr[i] = src[i];
    for (int i = t; i < 1024; i += 256) {
        int z = i >> 4, k = i & 15;
        int fk = k < 8 ? k : k - 16;
        float2 w = g_TW[(z * fk) & 63];
        tw[i] = make_float2(w.x, -w.y);           // e^{-i theta}
    }
    __syncthreads();
    int kz = t & 15, yg = t >> 4;
    float2 acc[4];
    #pragma unroll
    for (int j = 0; j < 4; j++) acc[j] = make_float2(0.f, 0.f);
    for (int z = 0; z < 64; z++) {
        float2 w = tw[z*16 + kz];
        #pragma unroll
        for (int j = 0; j < 4; j++) {
            float v = xr[(yg + 16*j)*64 + z];
            acc[j].x += v * w.x;
            acc[j].y += v * w.y;
        }
    }
    float2* dst = g_S1 + (size_t)blk * 1024;
    #pragma unroll
    for (int j = 0; j < 4; j++) dst[(yg + 16*j)*16 + kz] = acc[j];
}

// ---------------- K2: forward y-DFT (complex), 64 -> 16 ----------------
__global__ void k2_ydft() {
    __shared__ float2 tile[1024];
    __shared__ float2 tw[1024];
    int blk = blockIdx.x;           // bc*64 + x
    int t = threadIdx.x;            // 64 threads
    const float2* src = g_S1 + (size_t)blk * 1024;
    for (int i = t; i < 1024; i += 64) tile[i] = src[i];
    for (int i = t; i < 1024; i += 64) {
        int y = i >> 4, k = i & 15;
        int fk = k < 8 ? k : k - 16;
        float2 w = g_TW[(y * fk) & 63];
        tw[i] = make_float2(w.x, -w.y);
    }
    __syncthreads();
    int kyb = t >> 3, kzb = t & 7;
    float2 a00 = make_float2(0,0), a01 = make_float2(0,0);
    float2 a10 = make_float2(0,0), a11 = make_float2(0,0);
    for (int y = 0; y < 64; y++) {
        float2 w0 = tw[y*16 + kyb];
        float2 w1 = tw[y*16 + kyb + 8];
        float2 v0 = tile[y*16 + kzb];
        float2 v1 = tile[y*16 + kzb + 8];
        a00.x += v0.x*w0.x - v0.y*w0.y;  a00.y += v0.x*w0.y + v0.y*w0.x;
        a01.x += v1.x*w0.x - v1.y*w0.y;  a01.y += v1.x*w0.y + v1.y*w0.x;
        a10.x += v0.x*w1.x - v0.y*w1.y;  a10.y += v0.x*w1.y + v0.y*w1.x;
        a11.x += v1.x*w1.x - v1.y*w1.y;  a11.y += v1.x*w1.y + v1.y*w1.x;
    }
    float2* dst = g_S2 + (size_t)blk * 256;
    dst[kyb*16 + kzb]          = a00;
    dst[kyb*16 + kzb + 8]      = a01;
    dst[(kyb+8)*16 + kzb]      = a10;
    dst[(kyb+8)*16 + kzb + 8]  = a11;
}

// ---------------- K3: forward x-DFT (complex), 64 -> 16 ----------------
__global__ void k3_xdft() {
    __shared__ float2 tw[1024];
    int bc = blockIdx.x;
    int t = threadIdx.x;            // 256 threads: t = ky*16+kz
    for (int i = t; i < 1024; i += 256) {
        int xx = i >> 4, k = i & 15;
        int fk = k < 8 ? k : k - 16;
        float2 w = g_TW[(xx * fk) & 63];
        tw[i] = make_float2(w.x, -w.y);
    }
    __syncthreads();
    float2 acc[16];
    #pragma unroll
    for (int k = 0; k < 16; k++) acc[k] = make_float2(0.f, 0.f);
    const float2* src = g_S2 + (size_t)bc * 64 * 256;
    for (int xx = 0; xx < 64; xx++) {
        float2 v = src[xx*256 + t];
        #pragma unroll
        for (int kx = 0; kx < 16; kx++) {
            float2 w = tw[xx*16 + kx];
            acc[kx].x += v.x*w.x - v.y*w.y;
            acc[kx].y += v.x*w.y + v.y*w.x;
        }
    }
    float2* dst = g_XS + (size_t)bc * 4096;
    #pragma unroll
    for (int kx = 0; kx < 16; kx++) dst[t*16 + kx] = acc[kx];
}

// ---------------- K4: basis projection -> 144 coeffs ----------------
__global__ void k4_proj() {
    int bc = blockIdx.x;
    int k = threadIdx.x;
    if (k >= K144) return;
    int s = k / 9, l = k - s * 9;
    int beg = g_off[s], end = g_off[s+1];
    const float2* xs = g_XS + (size_t)bc * 4096;
    float ar = 0.f, ai = 0.f;
    for (int i = beg; i < end; i++) {
        int m = g_sorted[i];
        float w = g_YW[m*9 + l];
        int sidx = ((m & 255) << 4) | (m >> 8);
        float2 v = xs[sidx];
        ar += v.x * w;
        ai += v.y * w;
    }
    g_C1[bc*K144 + k] = make_float2(ar, ai);
}

// ---------------- K5: spectral channel conv (complex 32x32 per (b,s,l)) ----------------
__global__ void k5_conv(const float* __restrict__ wr, const float* __restrict__ wi) {
    __shared__ float2 cin[32];
    int blk = blockIdx.x;           // b*144 + sl
    int b = blk / K144, sl = blk - b * K144;
    int o = threadIdx.x;            // 32 threads
    cin[o] = g_C1[(b*32 + o)*K144 + sl];
    __syncthreads();
    const float* wrp = wr + (size_t)sl * 32 * 32 + o;   // [sl][i][o]
    const float* wip = wi + (size_t)sl * 32 * 32 + o;
    float ar = 0.f, ai = 0.f;
    #pragma unroll
    for (int i = 0; i < 32; i++) {
        float2 c = cin[i];
        float a = wrp[i*32], bb = wip[i*32];
        ar += c.x*a - c.y*bb;
        ai += c.x*bb + c.y*a;
    }
    const float invn = 1.0f / 262144.0f;   // fold 1/N^3 of ifftn here
    g_C2[(b*32 + o)*K144 + sl] = make_float2(ar*invn, ai*invn);
}

// ---------------- K6: inverse basis expansion + inverse x-DFT (16 -> 64) ----------------
__global__ void k6_invx() {
    __shared__ float2 c2[K144];
    __shared__ float2 tw[1024];
    int bo = blockIdx.x;            // b*32+o
    int t = threadIdx.x;            // 256 threads: t = ky*16+kz
    if (t < K144) c2[t] = g_C2[bo*K144 + t];
    for (int i = t; i < 1024; i += 256) {
        int xx = i >> 4, k = i & 15;
        int fk = k < 8 ? k : k - 16;
        float2 w = g_TW[(xx * fk) & 63];
        tw[i] = make_float2(w.x, w.y);            // e^{+i theta}
    }
    __syncthreads();
    float2 xs2[16];
    #pragma unroll
    for (int kx = 0; kx < 16; kx++) {
        int m = (kx << 8) | t;
        int s = g_shell[m];
        const float* yw = &g_YW[m*9];
        const float2* cc = &c2[s*9];
        float ar = 0.f, ai = 0.f;
        #pragma unroll
        for (int l = 0; l < 9; l++) {
            float w = yw[l];
            ar += cc[l].x * w;
            ai += cc[l].y * w;
        }
        xs2[kx] = make_float2(ar, ai);
    }
    float2* dst = g_T1 + (size_t)bo * 64 * 256;
    for (int xx = 0; xx < 64; xx++) {
        float ar = 0.f, ai = 0.f;
        #pragma unroll
        for (int kx = 0; kx < 16; kx++) {
            float2 w = tw[xx*16 + kx];
            ar += xs2[kx].x*w.x - xs2[kx].y*w.y;
            ai += xs2[kx].x*w.y + xs2[kx].y*w.x;
        }
        dst[xx*256 + t] = make_float2(ar, ai);
    }
}

// ---------------- K7: inverse y-DFT (16 -> 64) ----------------
__global__ void k7_invy() {
    __shared__ float2 tile[256];
    __shared__ float2 tw[1024];
    int blk = blockIdx.x;           // bo*64 + x
    int t = threadIdx.x;            // 256 threads
    const float2* src = g_T1 + (size_t)blk * 256;
    if (t < 256) tile[t] = src[t];
    for (int i = t; i < 1024; i += 256) {
        int y = i >> 4, k = i & 15;
        int fk = k < 8 ? k : k - 16;
        float2 w = g_TW[(y * fk) & 63];
        tw[i] = make_float2(w.x, w.y);
    }
    __syncthreads();
    int kz = t & 15, yg = t >> 4;
    float2* dst = g_T2 + (size_t)blk * 1024;
    #pragma unroll
    for (int j = 0; j < 4; j++) {
        int y = yg + 16*j;
        float2 acc = make_float2(0.f, 0.f);
        #pragma unroll
        for (int ky = 0; ky < 16; ky++) {
            float2 w = tw[y*16 + ky];
            float2 v = tile[ky*16 + kz];
            acc.x += v.x*w.x - v.y*w.y;
            acc.y += v.x*w.y + v.y*w.x;
        }
        dst[y*16 + kz] = acc;
    }
}

// ---------------- K8: inverse z-DFT fused with skips + complex MLP ----------------
__device__ __forceinline__ float gelu_t(float v) {
    float u = 0.7978845608028654f * (v + 0.044715f * v * v * v);
    return 0.5f * v * (1.0f + tanhf(u));
}

__global__ void k8_final(const float* __restrict__ x,
                         const float* __restrict__ wfr, const float* __restrict__ wfi,
                         const float* __restrict__ bfr, const float* __restrict__ bfi,
                         const float* __restrict__ wgr,
                         const float* __restrict__ w1r, const float* __restrict__ w1i,
                         const float* __restrict__ b1r, const float* __restrict__ b1i,
                         const float* __restrict__ w2r, const float* __restrict__ w2i,
                         const float* __restrict__ b2r,
                         float* __restrict__ out) {
    extern __shared__ char smem[];
    float2* s_t2 = (float2*)smem;            // 512  : [o][kz]
    float*  s_xr = (float*)(s_t2 + 512);     // 2048 : [c][z]
    float2* s_x1 = (float2*)(s_xr + 2048);   // 2048 : [o][z]
    float2* s_h  = s_x1 + 2048;              // 1024 : [j][z]
    float2* s_tw = s_h + 1024;               // 1024 : [kz][z]  e^{+i}
    float2* s_wf = s_tw + 1024;              // 1024 : wfno[o][c]
    float2* s_w1 = s_wf + 1024;              // 512  : w1[j][o]
    float2* s_w2 = s_w1 + 512;               // 512  : w2[o][j]
    float2* s_bf = s_w2 + 512;               // 32
    float2* s_b1 = s_bf + 32;                // 16
    float*  s_b2 = (float*)(s_b1 + 16);      // 32
    float*  s_wg = s_b2 + 32;                // 32

    int blk = blockIdx.x;
    int b = blk >> 12;
    int xc = (blk >> 6) & 63;
    int y  = blk & 63;
    int t = threadIdx.x;

    // loads
    for (int i = t; i < 512; i += 256) {
        int o = i >> 4, kz = i & 15;
        s_t2[i] = g_T2[((((size_t)(b*32 + o) * 64 + xc) * 64 + y) << 4) + kz];
    }
    for (int i = t; i < 2048; i += 256) {
        int c = i >> 6, z = i & 63;
        s_xr[i] = x[(size_t)(b*32 + c) * 262144 + (size_t)xc * 4096 + y * 64 + z];
    }
    for (int i = t; i < 1024; i += 256) {
        int kz = i >> 6, z = i & 63;
        int fk = kz < 8 ? kz : kz - 16;
        float2 w = g_TW[(z * fk) & 63];
        s_tw[i] = make_float2(w.x, w.y);
        s_wf[i] = make_float2(wfr[i], wfi[i]);
    }
    for (int i = t; i < 512; i += 256) {
        s_w1[i] = make_float2(w1r[i], w1i[i]);
        s_w2[i] = make_float2(w2r[i], w2i[i]);
    }
    if (t < 32) {
        s_bf[t] = make_float2(bfr[t], bfi[t]);
        s_b2[t] = b2r[t];
        s_wg[t] = wgr[t];
        if (t < 16) s_b1[t] = make_float2(b1r[t], b1i[t]);
    }
    __syncthreads();

    // pass 1: x1[o][z] = ifft_z(t2) + W_fno * x + b_fno
    {
        int z = t & 63, og = t >> 6;     // 8 o's per thread
        float2 acc[8];
        #pragma unroll
        for (int q = 0; q < 8; q++) {
            int o = og * 8 + q;
            acc[q] = s_bf[o];
        }
        #pragma unroll
        for (int kz = 0; kz < 16; kz++) {
            float2 w = s_tw[kz*64 + z];
            #pragma unroll
            for (int q = 0; q < 8; q++) {
                float2 v = s_t2[(og*8 + q)*16 + kz];
                acc[q].x += v.x*w.x - v.y*w.y;
                acc[q].y += v.x*w.y + v.y*w.x;
            }
        }
        for (int c = 0; c < 32; c++) {
            float xv = s_xr[c*64 + z];
            #pragma unroll
            for (int q = 0; q < 8; q++) {
                float2 w = s_wf[(og*8 + q)*32 + c];
                acc[q].x += w.x * xv;
                acc[q].y += w.y * xv;
            }
        }
        #pragma unroll
        for (int q = 0; q < 8; q++) s_x1[(og*8 + q)*64 + z] = acc[q];
    }
    __syncthreads();

    // pass 2: h[j][z] = cgelu(W1 * x1 + b1)
    {
        int z = t & 63, jg = t >> 6;     // 4 j's per thread
        float hr[4], hi[4];
        #pragma unroll
        for (int p = 0; p < 4; p++) {
            int j = jg * 4 + p;
            hr[p] = s_b1[j].x;
            hi[p] = s_b1[j].y;
        }
        for (int o = 0; o < 32; o++) {
            float2 v = s_x1[o*64 + z];
            #pragma unroll
            for (int p = 0; p < 4; p++) {
                float2 w = s_w1[(jg*4 + p)*32 + o];
                hr[p] += w.x*v.x - w.y*v.y;
                hi[p] += w.x*v.y + w.y*v.x;
            }
        }
        #pragma unroll
        for (int p = 0; p < 4; p++)
            s_h[(jg*4 + p)*64 + z] = make_float2(gelu_t(hr[p]), gelu_t(hi[p]));
    }
    __syncthreads();

    // pass 3: out = Re(W2*h + b2) + x*w_gate_r
    {
        int z = t & 63, og = t >> 6;     // 8 o's per thread
        float acc[8];
        #pragma unroll
        for (int q = 0; q < 8; q++) acc[q] = s_b2[og*8 + q];
        #pragma unroll
        for (int j = 0; j < 16; j++) {
            float2 hv = s_h[j*64 + z];
            #pragma unroll
            for (int q = 0; q < 8; q++) {
                float2 w = s_w2[(og*8 + q)*16 + j];
                acc[q] += w.x*hv.x - w.y*hv.y;
            }
        }
        #pragma unroll
        for (int q = 0; q < 8; q++) {
            int o = og * 8 + q;
            acc[q] += s_xr[o*64 + z] * s_wg[o];
            out[(size_t)(b*32 + o) * 262144 + (size_t)xc * 4096 + y * 64 + z] = acc[q];
        }
    }
}

// ---------------- launch ----------------
extern "C" void kernel_launch(void* const* d_in, const int* in_sizes, int n_in,
                              void* d_out, int out_size) {
    const float* x    = (const float*)d_in[0];
    const float* wfr  = (const float*)d_in[1];
    const float* wfi  = (const float*)d_in[2];
    const float* bfr  = (const float*)d_in[3];
    const float* bfi  = (const float*)d_in[4];
    const float* wgr  = (const float*)d_in[5];
    /* w_gate_i (d_in[6]) unused: output takes real part only */
    const float* wsr  = (const float*)d_in[7];
    const float* wsi  = (const float*)d_in[8];
    const float* w1r  = (const float*)d_in[9];
    const float* w1i  = (const float*)d_in[10];
    const float* b1r  = (const float*)d_in[11];
    const float* b1i  = (const float*)d_in[12];
    const float* w2r  = (const float*)d_in[13];
    const float* w2i  = (const float*)d_in[14];
    const float* b2r  = (const float*)d_in[15];
    /* mlp_b2_i (d_in[16]) unused: output real part only */
    float* out = (float*)d_out;

    cudaFuncSetAttribute(k8_final, cudaFuncAttributeMaxDynamicSharedMemorySize, 65536);

    k0_init<<<1, 256>>>();
    k1_zdft<<<BB*CC*64, 256>>>(x);
    k2_ydft<<<BB*CC*64, 64>>>();
    k3_xdft<<<BB*CC, 256>>>();
    k4_proj<<<BB*CC, 160>>>();
    k5_conv<<<BB*K144, 32>>>(wsr, wsi);
    k6_invx<<<BB*COC, 256>>>();
    k7_invy<<<BB*COC*64, 256>>>();
    k8_final<<<BB*64*64, 256, 62080>>>(x, wfr, wfi, bfr, bfi, wgr,
                                       w1r, w1i, b1r, b1i, w2r, w2i, b2r, out);
}

// round 3
// speedup vs baseline: 1.1906x; 1.1906x over previous
#include <cuda_runtime.h>
#include <math.h>

// ---------------- problem constants ----------------
#define BB 2
#define CC 32
#define COC 32
#define HID 16
#define K144 144
#define M4096 4096

// ---------------- device scratch ----------------
__device__ float2 g_S2[BB*CC*64*256];     // after y-DFT  [bc][x][ky*16+kz]
__device__ float2 g_XS[BB*CC*M4096];      // spectral modes [bc][m]  (m = kx*256+ky*16+kz)
__device__ float2 g_C1[BB*CC*K144];       // coeffs  [b][c][s*9+l]
__device__ float2 g_C3[BB*HID*K144];      // W1-applied coeffs [b][j][s*9+l]
__device__ float2 g_T2[BB*64*64*256];     // [b][x][y][j*16+kz]  (j-interleaved)
__device__ int    g_shell[M4096];
__device__ float  g_YW[M4096*9];          // w[shell]*Y[l], mode order
__device__ float  g_YWs[M4096*9];         // same, shell-sorted order
__device__ int    g_sorted[M4096];
__device__ int    g_off[17];
__device__ float2 g_TW[64];               // e^{+2*pi*i*j/64}
__device__ float2 g_WC[HID*CC];           // W1 @ W_fno  (complex 16x32)
__device__ float2 g_BC[HID];              // W1 @ b_fno + b1

// ---------------- K0: tables (deterministic) ----------------
__global__ void k0_init() {
    __shared__ int cnt[16];
    __shared__ float wS[16];
    __shared__ int off[17];
    int t = threadIdx.x;                      // 512 threads
    if (t < 16) cnt[t] = 0;
    __syncthreads();
    for (int m = t; m < M4096; m += 512) {
        int ix = m >> 8, iy = (m >> 4) & 15, iz = m & 15;
        int fx = ix < 8 ? ix : ix - 16;
        int fy = iy < 8 ? iy : iy - 16;
        int fz = iz < 8 ? iz : iz - 16;
        int k2 = fx*fx + fy*fy + fz*fz;
        double r = sqrt((double)k2);
        double denom = (double)sqrtf(192.0f) + 1e-6;
        int s = (int)(r / denom * 16.0);
        if (s > 15) s = 15;
        g_shell[m] = s;
        atomicAdd(&cnt[s], 1);
        float inv = k2 > 0 ? (float)(1.0 / r) : 0.0f;
        float ux = fx * inv, uy = fy * inv, uz = fz * inv;
        float nzm = k2 > 0 ? 1.0f : 0.0f;
        float* Y = &g_YW[m * 9];
        Y[0] = 0.282095f;
        Y[1] = 0.488603f * uy;
        Y[2] = 0.488603f * uz;
        Y[3] = 0.488603f * ux;
        Y[4] = 1.092548f * ux * uy;
        Y[5] = 1.092548f * uy * uz;
        Y[6] = 0.315392f * (3.0f * uz * uz - nzm);
        Y[7] = 1.092548f * ux * uz;
        Y[8] = 0.546274f * (ux * ux - uy * uy);
    }
    __syncthreads();
    if (t < 16) wS[t] = 1.0f / sqrtf(fmaxf((float)cnt[t], 1.0f));
    if (t == 0) {
        int acc = 0;
        for (int s = 0; s < 16; s++) { off[s] = acc; g_off[s] = acc; acc += cnt[s]; }
        off[16] = acc; g_off[16] = acc;
    }
    __syncthreads();
    for (int m = t; m < M4096; m += 512) {
        float w = wS[g_shell[m]];
        #pragma unroll
        for (int l = 0; l < 9; l++) g_YW[m*9+l] *= w;
    }
    __syncthreads();
    // deterministic shell-sort: one warp per shell, ballot-prefix positions
    {
        int w = t >> 5, lane = t & 31;
        int s = w;                             // 16 warps, 16 shells
        int pos = off[s];
        for (int chunk = 0; chunk < 128; chunk++) {
            int m = chunk * 32 + lane;
            bool mine = (g_shell[m] == s);
            unsigned msk = __ballot_sync(0xffffffffu, mine);
            if (mine) {
                int p = pos + __popc(msk & ((1u << lane) - 1u));
                g_sorted[p] = m;
                #pragma unroll
                for (int l = 0; l < 9; l++) g_YWs[p*9+l] = g_YW[m*9+l];
            }
            pos += __popc(msk);
        }
    }
    if (t < 64) {
        float ang = (float)(2.0 * M_PI * (double)t / 64.0);
        g_TW[t] = make_float2(cosf(ang), sinf(ang));
    }
}

// ---------------- Kpre: fold W1 into the FNO skip ----------------
__global__ void kpre(const float* __restrict__ wfr, const float* __restrict__ wfi,
                     const float* __restrict__ bfr, const float* __restrict__ bfi,
                     const float* __restrict__ w1r, const float* __restrict__ w1i,
                     const float* __restrict__ b1r, const float* __restrict__ b1i) {
    int t = threadIdx.x;                 // 512 threads: (j, c)
    int j = t >> 5, c = t & 31;
    float ar = 0.f, ai = 0.f;
    for (int o = 0; o < 32; o++) {
        float ax = w1r[j*32+o], ay = w1i[j*32+o];
        float bx = wfr[o*32+c], by = wfi[o*32+c];
        ar += ax*bx - ay*by;
        ai += ax*by + ay*bx;
    }
    g_WC[j*32+c] = make_float2(ar, ai);
    if (c == 0) {
        float br = b1r[j], bi = b1i[j];
        for (int o = 0; o < 32; o++) {
            float ax = w1r[j*32+o], ay = w1i[j*32+o];
            float bx = bfr[o], by = bfi[o];
            br += ax*bx - ay*by;
            bi += ax*by + ay*bx;
        }
        g_BC[j] = make_float2(br, bi);
    }
}

// ---------------- K12: fused forward z-DFT (real, conj-symmetric) + y-DFT ----------------
__global__ void k12_fwd(const float* __restrict__ x) {
    __shared__ float  xp[64*65];     // padded plane [y][z]
    __shared__ float2 S1[1024];      // [y][kz]
    __shared__ float2 twf[1024];     // e^{-2pi i fk j/64}, [k*64+j]
    int blk = blockIdx.x;            // bc*64 + x
    int t = threadIdx.x;             // 256
    const float* src = x + (size_t)blk * 4096;
    for (int i = t; i < 4096; i += 256) xp[(i >> 6)*65 + (i & 63)] = src[i];
    for (int i = t; i < 1024; i += 256) {
        int k = i >> 6, j = i & 63;
        int fk = k < 8 ? k : k - 16;
        float2 w = g_TW[(j * fk) & 63];
        twf[i] = make_float2(w.x, -w.y);
    }
    __syncthreads();
    // phase A: z-DFT with conjugate symmetry (compute kz = q, q+4, and 8 if q==0)
    {
        int y = t >> 2, q = t & 3;
        float c0=0.f,s0=0.f,c1=0.f,s1=0.f,c2=0.f,s2=0.f;
        const float* row = &xp[y*65];
        for (int z = 0; z < 64; z++) {
            float xv = row[z];
            float2 w0 = twf[q*64 + z];
            float2 w1 = twf[(q+4)*64 + z];
            c0 += xv*w0.x; s0 += xv*w0.y;
            c1 += xv*w1.x; s1 += xv*w1.y;
            if (q == 0) { float2 w2 = twf[8*64 + z]; c2 += xv*w2.x; s2 += xv*w2.y; }
        }
        S1[y*16 + q]     = make_float2(c0, s0);
        S1[y*16 + q + 4] = make_float2(c1, s1);
        S1[y*16 + 12 - q] = make_float2(c1, -s1);
        if (q > 0) S1[y*16 + 16 - q] = make_float2(c0, -s0);
        else       S1[y*16 + 8]      = make_float2(c2, s2);
    }
    __syncthreads();
    // phase B: y-DFT (complex), one output per thread
    {
        int ky = t >> 4, kz = t & 15;
        float ar = 0.f, ai = 0.f;
        for (int y = 0; y < 64; y++) {
            float2 v = S1[y*16 + kz];
            float2 w = twf[ky*64 + y];
            ar += v.x*w.x - v.y*w.y;
            ai += v.x*w.y + v.y*w.x;
        }
        g_S2[(size_t)blk * 256 + t] = make_float2(ar, ai);
    }
}

// ---------------- K3: forward x-DFT (reduce over x), 256 blocks ----------------
__global__ void k3_xdft() {
    __shared__ float2 tw[1024];      // e^{-i}, [kx*64+xx]
    int bc = blockIdx.x >> 2;
    int tq = blockIdx.x & 3;
    int tid = threadIdx.x;           // 256: kxg(4) x tl(64)
    int kxg = tid >> 6, tl = tid & 63;
    int t = tq * 64 + tl;
    for (int i = tid; i < 1024; i += 256) {
        int k = i >> 6, j = i & 63;
        int fk = k < 8 ? k : k - 16;
        float2 w = g_TW[(j * fk) & 63];
        tw[i] = make_float2(w.x, -w.y);
    }
    __syncthreads();
    float2 acc[4];
    #pragma unroll
    for (int i = 0; i < 4; i++) acc[i] = make_float2(0.f, 0.f);
    const float2* src = g_S2 + (size_t)bc * 16384;
    for (int xx = 0; xx < 64; xx++) {
        float2 v = src[xx*256 + t];
        #pragma unroll
        for (int i = 0; i < 4; i++) {
            float2 w = tw[(kxg*4 + i)*64 + xx];
            acc[i].x += v.x*w.x - v.y*w.y;
            acc[i].y += v.x*w.y + v.y*w.x;
        }
    }
    float2* dst = g_XS + (size_t)bc * 4096;
    #pragma unroll
    for (int i = 0; i < 4; i++) dst[(kxg*4 + i)*256 + t] = acc[i];
}

// ---------------- K4: basis projection -> 144 coeffs ----------------
__global__ void k4_proj() {
    __shared__ float2 sxs[4096];     // full spectrum for this (b,c)
    __shared__ float2 part[4*K144];
    int bc = blockIdx.x;
    int tid = threadIdx.x;           // 576 threads
    for (int i = tid; i < 4096; i += 576) sxs[i] = g_XS[(size_t)bc * 4096 + i];
    __syncthreads();
    int p = tid / K144, k = tid - p * K144;   // p in 0..3
    {
        int s = k / 9, l = k - s * 9;
        int beg = g_off[s], end = g_off[s+1], len = end - beg;
        int i0 = beg + (len * p) / 4;
        int i1 = beg + (len * (p + 1)) / 4;
        float ar = 0.f, ai = 0.f;
        for (int i = i0; i < i1; i++) {
            int m = g_sorted[i];
            float w = g_YWs[i*9 + l];
            float2 v = sxs[m];
            ar += v.x * w;
            ai += v.y * w;
        }
        part[p*K144 + k] = make_float2(ar, ai);
    }
    __syncthreads();
    if (tid < K144) {
        float2 a = part[tid];
        float2 b = part[K144 + tid];
        float2 c = part[2*K144 + tid];
        float2 d = part[3*K144 + tid];
        g_C1[(size_t)bc*K144 + tid] = make_float2(a.x+b.x+c.x+d.x, a.y+b.y+c.y+d.y);
    }
}

// ---------------- K5: spectral conv (32->32) fused with W1 (32->16) ----------------
__global__ void k5_conv(const float* __restrict__ wr, const float* __restrict__ wi,
                        const float* __restrict__ w1r, const float* __restrict__ w1i) {
    __shared__ float2 cin[32];
    __shared__ float2 c2s[32];
    int blk = blockIdx.x;            // b*144 + sl
    int b = blk / K144, sl = blk - b * K144;
    int o = threadIdx.x;             // 32 threads
    cin[o] = g_C1[((size_t)(b*32 + o))*K144 + sl];
    __syncwarp();
    const float* wrp = wr + (size_t)sl * 1024 + o;
    const float* wip = wi + (size_t)sl * 1024 + o;
    float ar = 0.f, ai = 0.f;
    #pragma unroll
    for (int i = 0; i < 32; i++) {
        float2 c = cin[i];
        float a = wrp[i*32], bb = wip[i*32];
        ar += c.x*a - c.y*bb;
        ai += c.x*bb + c.y*a;
    }
    const float invn = 1.0f / 262144.0f;
    c2s[o] = make_float2(ar*invn, ai*invn);
    __syncwarp();
    if (o < HID) {
        int j = o;
        float br = 0.f, bi = 0.f;
        #pragma unroll
        for (int q = 0; q < 32; q++) {
            float ax = w1r[j*32+q], ay = w1i[j*32+q];
            float2 c = c2s[q];
            br += ax*c.x - ay*c.y;
            bi += ax*c.y + ay*c.x;
        }
        g_C3[((size_t)(b*HID + j))*K144 + sl] = make_float2(br, bi);
    }
}

// ---------------- K67: inverse basis + inverse x-DFT + inverse y-DFT ----------------
__global__ void k67_inv() {
    __shared__ float2 c3[K144];
    __shared__ float2 twi[1024];     // e^{+i}, [k*64+j]
    __shared__ float2 S[256];        // [ky][kz]
    int bj = blockIdx.x >> 3;        // b*16 + j
    int xch = blockIdx.x & 7;
    int b = bj >> 4, j = bj & 15;
    int t = threadIdx.x;             // 256
    if (t < K144) c3[t] = g_C3[(size_t)bj*K144 + t];
    for (int i = t; i < 1024; i += 256) {
        int k = i >> 6, jj = i & 63;
        int fk = k < 8 ? k : k - 16;
        twi[i] = g_TW[(jj * fk) & 63];
    }
    __syncthreads();
    // inverse basis: xs2[kx] for my t = ky*16+kz
    float2 xs2[16];
    #pragma unroll
    for (int kx = 0; kx < 16; kx++) {
        int m = (kx << 8) | t;
        int s = g_shell[m];
        const float* yw = &g_YW[m*9];
        const float2* cc = &c3[s*9];
        float ar = 0.f, ai = 0.f;
        #pragma unroll
        for (int l = 0; l < 9; l++) {
            float w = yw[l];
            ar += cc[l].x * w;
            ai += cc[l].y * w;
        }
        xs2[kx] = make_float2(ar, ai);
    }
    for (int xi = 0; xi < 8; xi++) {
        int xx = xch * 8 + xi;
        float2 o = make_float2(0.f, 0.f);
        #pragma unroll
        for (int kx = 0; kx < 16; kx++) {
            float2 w = twi[kx*64 + xx];
            o.x += xs2[kx].x*w.x - xs2[kx].y*w.y;
            o.y += xs2[kx].x*w.y + xs2[kx].y*w.x;
        }
        S[t] = o;
        __syncthreads();
        // inverse y-DFT: outputs [64y][16kz]
        {
            int y = t & 63, kzg = t >> 6;
            float2 acc[4];
            #pragma unroll
            for (int i = 0; i < 4; i++) acc[i] = make_float2(0.f, 0.f);
            for (int ky = 0; ky < 16; ky++) {
                float2 w = twi[ky*64 + y];
                #pragma unroll
                for (int i = 0; i < 4; i++) {
                    float2 v = S[ky*16 + kzg*4 + i];
                    acc[i].x += v.x*w.x - v.y*w.y;
                    acc[i].y += v.x*w.y + v.y*w.x;
                }
            }
            size_t base = (((size_t)b*64 + xx)*64 + y)*256 + j*16 + kzg*4;
            #pragma unroll
            for (int i = 0; i < 4; i++) g_T2[base + i] = acc[i];
        }
        __syncthreads();
    }
}

// ---------------- K8: z-inverse DFT + fused skip/GELU/W2 epilogue ----------------
__device__ __forceinline__ float gelu_t(float v) {
    float u = 0.7978845608028654f * (v + 0.044715f * v * v * v);
    return 0.5f * v * (1.0f + tanhf(u));
}

__global__ void k8_final(const float* __restrict__ x,
                         const float* __restrict__ wgr,
                         const float* __restrict__ w2r, const float* __restrict__ w2i,
                         const float* __restrict__ b2r,
                         float* __restrict__ out) {
    __shared__ float2 s_t2[256];     // [j][kz]
    __shared__ float  s_x[2048];     // [c][z]
    __shared__ float2 s_tw[1024];    // e^{+i}, [kz][z]
    __shared__ float2 s_h[1024];     // [j][z]
    __shared__ float2 s_wc[512];     // [j][c]
    __shared__ float2 s_w2[512];     // [o][j]
    __shared__ float2 s_bc[16];
    __shared__ float  s_b2[32];
    __shared__ float  s_wg[32];

    int blk = blockIdx.x;
    int b = blk >> 12;
    int xc = (blk >> 6) & 63;
    int y  = blk & 63;
    int t = threadIdx.x;             // 256

    {
        size_t base = (((size_t)b*64 + xc)*64 + y)*256;
        s_t2[t] = g_T2[base + t];
    }
    for (int i = t; i < 2048; i += 256) {
        int c = i >> 6, z = i & 63;
        s_x[i] = x[(((size_t)(b*32 + c))*64 + xc)*4096 + y*64 + z];
    }
    for (int i = t; i < 1024; i += 256) {
        int kz = i >> 6, z = i & 63;
        int fk = kz < 8 ? kz : kz - 16;
        s_tw[i] = g_TW[(z * fk) & 63];
    }
    for (int i = t; i < 512; i += 256) {
        s_wc[i] = g_WC[i];
        s_w2[i] = make_float2(w2r[i], w2i[i]);
    }
    if (t < 32) {
        s_b2[t] = b2r[t];
        s_wg[t] = wgr[t];
        if (t < 16) s_bc[t] = g_BC[t];
    }
    __syncthreads();

    // pass 1: g[j][z] = ifft_z(t2) + Wc*x + bc ; h = cgelu(g)
    {
        int jg = t >> 6, z = t & 63;
        float2 acc[4];
        #pragma unroll
        for (int p = 0; p < 4; p++) acc[p] = s_bc[jg*4 + p];
        #pragma unroll
        for (int kz = 0; kz < 16; kz++) {
            float2 w = s_tw[kz*64 + z];
            #pragma unroll
            for (int p = 0; p < 4; p++) {
                float2 v = s_t2[(jg*4 + p)*16 + kz];
                acc[p].x += v.x*w.x - v.y*w.y;
                acc[p].y += v.x*w.y + v.y*w.x;
            }
        }
        #pragma unroll 4
        for (int c = 0; c < 32; c++) {
            float xv = s_x[c*64 + z];
            #pragma unroll
            for (int p = 0; p < 4; p++) {
                float2 w = s_wc[(jg*4 + p)*32 + c];
                acc[p].x += w.x * xv;
                acc[p].y += w.y * xv;
            }
        }
        #pragma unroll
        for (int p = 0; p < 4; p++)
            s_h[(jg*4 + p)*64 + z] = make_float2(gelu_t(acc[p].x), gelu_t(acc[p].y));
    }
    __syncthreads();

    // pass 2: out[o][z] = Re(W2 h) + b2r + x*w_gate_r
    {
        int og = t >> 6, z = t & 63;
        float acc[8];
        #pragma unroll
        for (int q = 0; q < 8; q++) {
            int o = og*8 + q;
            acc[q] = s_b2[o] + s_x[o*64 + z] * s_wg[o];
        }
        #pragma unroll
        for (int j = 0; j < 16; j++) {
            float2 hv = s_h[j*64 + z];
            #pragma unroll
            for (int q = 0; q < 8; q++) {
                float2 w = s_w2[(og*8 + q)*16 + j];
                acc[q] += w.x*hv.x - w.y*hv.y;
            }
        }
        #pragma unroll
        for (int q = 0; q < 8; q++) {
            int o = og*8 + q;
            out[(((size_t)(b*32 + o))*64 + xc)*4096 + y*64 + z] = acc[q];
        }
    }
}

// ---------------- launch ----------------
extern "C" void kernel_launch(void* const* d_in, const int* in_sizes, int n_in,
                              void* d_out, int out_size) {
    const float* x    = (const float*)d_in[0];
    const float* wfr  = (const float*)d_in[1];
    const float* wfi  = (const float*)d_in[2];
    const float* bfr  = (const float*)d_in[3];
    const float* bfi  = (const float*)d_in[4];
    const float* wgr  = (const float*)d_in[5];
    const float* wsr  = (const float*)d_in[7];
    const float* wsi  = (const float*)d_in[8];
    const float* w1r  = (const float*)d_in[9];
    const float* w1i  = (const float*)d_in[10];
    const float* b1r  = (const float*)d_in[11];
    const float* b1i  = (const float*)d_in[12];
    const float* w2r  = (const float*)d_in[13];
    const float* w2i  = (const float*)d_in[14];
    const float* b2r  = (const float*)d_in[15];
    float* out = (float*)d_out;

    k0_init<<<1, 512>>>();
    kpre<<<1, 512>>>(wfr, wfi, bfr, bfi, w1r, w1i, b1r, b1i);
    k12_fwd<<<BB*CC*64, 256>>>(x);
    k3_xdft<<<BB*CC*4, 256>>>();
    k4_proj<<<BB*CC, 576>>>();
    k5_conv<<<BB*K144, 32>>>(wsr, wsi, w1r, w1i);
    k67_inv<<<BB*HID*8, 256>>>();
    k8_final<<<BB*64*64, 256>>>(x, wgr, w2r, w2i, b2r, out);
}

// round 4
// speedup vs baseline: 1.2036x; 1.0109x over previous
#include <cuda_runtime.h>
#include <math.h>

// ---------------- problem constants ----------------
#define BB 2
#define CC 32
#define COC 32
#define HID 16
#define K144 144
#define M4096 4096

typedef unsigned long long ull;

// ---------------- packed f32x2 helpers ----------------
__device__ __forceinline__ ull pk(float lo, float hi) {
    ull r; asm("mov.b64 %0, {%1,%2};" : "=l"(r) : "f"(lo), "f"(hi)); return r;
}
__device__ __forceinline__ ull splat(float v) { return pk(v, v); }
__device__ __forceinline__ float2 upk(ull v) {
    float2 r; asm("mov.b64 {%0,%1}, %2;" : "=f"(r.x), "=f"(r.y) : "l"(v)); return r;
}
__device__ __forceinline__ ull ffma2(ull a, ull b, ull c) {
    ull d; asm("fma.rn.f32x2 %0, %1, %2, %3;" : "=l"(d) : "l"(a), "l"(b), "l"(c)); return d;
}

// ---------------- device scratch ----------------
__device__ float2 g_S2[BB*CC*64*256];     // after y-DFT  [bc][x][ky*16+kz]
__device__ float2 g_XS[BB*CC*M4096];      // spectral modes [bc][m]
__device__ float2 g_C1P[BB*CC*4*K144];    // partial coeffs [bc][p][k]
__device__ float2 g_C3[BB*HID*K144];      // W1-applied coeffs [b][j][s*9+l]
__device__ float2 g_T2[BB*64*64*256];     // [b][x][y][j*16+kz]
__device__ int    g_shell[M4096];
__device__ float  g_YW[M4096*9];
__device__ float  g_YWs[M4096*9];
__device__ int    g_sorted[M4096];
__device__ int    g_off[17];
__device__ float2 g_TW[64];               // e^{+2*pi*i*j/64}
__device__ float2 g_WC[HID*CC];           // W1 @ W_fno
__device__ float2 g_BC[HID];              // W1 @ b_fno + b1

// ---------------- K0: tables ----------------
__global__ void k0_init() {
    __shared__ int cnt[16];
    __shared__ float wS[16];
    __shared__ int off[17];
    int t = threadIdx.x;                      // 512
    if (t < 16) cnt[t] = 0;
    __syncthreads();
    for (int m = t; m < M4096; m += 512) {
        int ix = m >> 8, iy = (m >> 4) & 15, iz = m & 15;
        int fx = ix < 8 ? ix : ix - 16;
        int fy = iy < 8 ? iy : iy - 16;
        int fz = iz < 8 ? iz : iz - 16;
        int k2 = fx*fx + fy*fy + fz*fz;
        double r = sqrt((double)k2);
        double denom = (double)sqrtf(192.0f) + 1e-6;
        int s = (int)(r / denom * 16.0);
        if (s > 15) s = 15;
        g_shell[m] = s;
        atomicAdd(&cnt[s], 1);
        float inv = k2 > 0 ? (float)(1.0 / r) : 0.0f;
        float ux = fx * inv, uy = fy * inv, uz = fz * inv;
        float nzm = k2 > 0 ? 1.0f : 0.0f;
        float* Y = &g_YW[m * 9];
        Y[0] = 0.282095f;
        Y[1] = 0.488603f * uy;
        Y[2] = 0.488603f * uz;
        Y[3] = 0.488603f * ux;
        Y[4] = 1.092548f * ux * uy;
        Y[5] = 1.092548f * uy * uz;
        Y[6] = 0.315392f * (3.0f * uz * uz - nzm);
        Y[7] = 1.092548f * ux * uz;
        Y[8] = 0.546274f * (ux * ux - uy * uy);
    }
    __syncthreads();
    if (t < 16) wS[t] = 1.0f / sqrtf(fmaxf((float)cnt[t], 1.0f));
    if (t == 0) {
        int acc = 0;
        for (int s = 0; s < 16; s++) { off[s] = acc; g_off[s] = acc; acc += cnt[s]; }
        off[16] = acc; g_off[16] = acc;
    }
    __syncthreads();
    for (int m = t; m < M4096; m += 512) {
        float w = wS[g_shell[m]];
        #pragma unroll
        for (int l = 0; l < 9; l++) g_YW[m*9+l] *= w;
    }
    __syncthreads();
    {
        int w = t >> 5, lane = t & 31;
        int s = w;
        int pos = off[s];
        for (int chunk = 0; chunk < 128; chunk++) {
            int m = chunk * 32 + lane;
            bool mine = (g_shell[m] == s);
            unsigned msk = __ballot_sync(0xffffffffu, mine);
            if (mine) {
                int p = pos + __popc(msk & ((1u << lane) - 1u));
                g_sorted[p] = m;
                #pragma unroll
                for (int l = 0; l < 9; l++) g_YWs[p*9+l] = g_YW[m*9+l];
            }
            pos += __popc(msk);
        }
    }
    if (t < 64) {
        float ang = (float)(2.0 * M_PI * (double)t / 64.0);
        g_TW[t] = make_float2(cosf(ang), sinf(ang));
    }
}

// ---------------- Kpre: fold W1 into the FNO skip ----------------
__global__ void kpre(const float* __restrict__ wfr, const float* __restrict__ wfi,
                     const float* __restrict__ bfr, const float* __restrict__ bfi,
                     const float* __restrict__ w1r, const float* __restrict__ w1i,
                     const float* __restrict__ b1r, const float* __restrict__ b1i) {
    int t = threadIdx.x;                 // 512
    int j = t >> 5, c = t & 31;
    float ar = 0.f, ai = 0.f;
    for (int o = 0; o < 32; o++) {
        float ax = w1r[j*32+o], ay = w1i[j*32+o];
        float bx = wfr[o*32+c], by = wfi[o*32+c];
        ar += ax*bx - ay*by;
        ai += ax*by + ay*bx;
    }
    g_WC[j*32+c] = make_float2(ar, ai);
    if (c == 0) {
        float br = b1r[j], bi = b1i[j];
        for (int o = 0; o < 32; o++) {
            float ax = w1r[j*32+o], ay = w1i[j*32+o];
            float bx = bfr[o], by = bfi[o];
            br += ax*bx - ay*by;
            bi += ax*by + ay*bx;
        }
        g_BC[j] = make_float2(br, bi);
    }
}

// ---------------- K12: fused forward z-DFT (conj-sym) + y-DFT, packed ----------------
__global__ void k12_fwd(const float* __restrict__ x) {
    __shared__ float  xp[64*65];
    __shared__ float2 S1[1024];
    __shared__ ull    twA[1024];     // (c, -s)
    __shared__ ull    twB[1024];     // (s, c)
    int blk = blockIdx.x;            // bc*64 + x
    int t = threadIdx.x;             // 256
    const float* src = x + (size_t)blk * 4096;
    for (int i = t; i < 4096; i += 256) xp[(i >> 6)*65 + (i & 63)] = src[i];
    for (int i = t; i < 1024; i += 256) {
        int k = i >> 6, j = i & 63;
        int fk = k < 8 ? k : k - 16;
        float2 w = g_TW[(j * fk) & 63];
        twA[i] = pk(w.x, -w.y);
        twB[i] = pk(w.y, w.x);
    }
    __syncthreads();
    // phase A: real z-DFT with conjugate symmetry
    {
        int y = t >> 2, q = t & 3;
        ull a0 = 0, a1 = 0, a2 = 0;
        const float* row = &xp[y*65];
        for (int z = 0; z < 64; z++) {
            ull sx = splat(row[z]);
            a0 = ffma2(sx, twA[q*64 + z], a0);
            a1 = ffma2(sx, twA[(q+4)*64 + z], a1);
            if (q == 0) a2 = ffma2(sx, twA[8*64 + z], a2);
        }
        float2 v0 = upk(a0), v1 = upk(a1), v2 = upk(a2);
        S1[y*16 + q]      = v0;
        S1[y*16 + q + 4]  = v1;
        S1[y*16 + 12 - q] = make_float2(v1.x, -v1.y);
        if (q > 0) S1[y*16 + 16 - q] = make_float2(v0.x, -v0.y);
        else       S1[y*16 + 8]      = v2;
    }
    __syncthreads();
    // phase B: complex y-DFT, packed
    {
        int ky = t >> 4, kz = t & 15;
        ull acc = 0;
        for (int y = 0; y < 64; y++) {
            float2 v = S1[y*16 + kz];
            acc = ffma2(splat(v.x), twA[ky*64 + y], acc);
            acc = ffma2(splat(v.y), twB[ky*64 + y], acc);
        }
        g_S2[(size_t)blk * 256 + t] = upk(acc);
    }
}

// ---------------- K3: forward x-DFT, packed ----------------
__global__ void k3_xdft() {
    __shared__ ull twA[1024];        // (c, -s), [kx*64+xx]
    __shared__ ull twB[1024];        // (s, c)
    int bc = blockIdx.x >> 2;
    int tq = blockIdx.x & 3;
    int tid = threadIdx.x;           // 256
    int kxg = tid >> 6, tl = tid & 63;
    int t = tq * 64 + tl;
    for (int i = tid; i < 1024; i += 256) {
        int k = i >> 6, j = i & 63;
        int fk = k < 8 ? k : k - 16;
        float2 w = g_TW[(j * fk) & 63];
        twA[i] = pk(w.x, -w.y);
        twB[i] = pk(w.y, w.x);
    }
    __syncthreads();
    ull acc[4] = {0, 0, 0, 0};
    const float2* src = g_S2 + (size_t)bc * 16384;
    for (int xx = 0; xx < 64; xx++) {
        float2 v = src[xx*256 + t];
        ull sx = splat(v.x), sy = splat(v.y);
        #pragma unroll
        for (int i = 0; i < 4; i++) {
            acc[i] = ffma2(sx, twA[(kxg*4 + i)*64 + xx], acc[i]);
            acc[i] = ffma2(sy, twB[(kxg*4 + i)*64 + xx], acc[i]);
        }
    }
    float2* dst = g_XS + (size_t)bc * 4096;
    #pragma unroll
    for (int i = 0; i < 4; i++) dst[(kxg*4 + i)*256 + t] = upk(acc[i]);
}

// ---------------- K4: basis projection (4-way split across blocks) ----------------
__global__ void k4_proj() {
    __shared__ float2 sxs[4096];
    int bc = blockIdx.x >> 2;
    int p  = blockIdx.x & 3;
    int tid = threadIdx.x;           // 256
    for (int i = tid; i < 4096; i += 256) sxs[i] = g_XS[(size_t)bc * 4096 + i];
    __syncthreads();
    if (tid < K144) {
        int k = tid;
        int s = k / 9, l = k - s * 9;
        int beg = g_off[s], end = g_off[s+1], len = end - beg;
        int i0 = beg + (len * p) / 4;
        int i1 = beg + (len * (p + 1)) / 4;
        ull acc = 0;
        for (int i = i0; i < i1; i++) {
            int m = g_sorted[i];
            float w = g_YWs[i*9 + l];
            float2 v = sxs[m];
            acc = ffma2(splat(w), pk(v.x, v.y), acc);
        }
        g_C1P[((size_t)bc*4 + p)*K144 + k] = upk(acc);
    }
}

// ---------------- K5: spectral conv fused with W1 ----------------
__global__ void k5_conv(const float* __restrict__ wr, const float* __restrict__ wi,
                        const float* __restrict__ w1r, const float* __restrict__ w1i) {
    __shared__ float2 cin[32];
    __shared__ float2 c2s[32];
    int blk = blockIdx.x;            // b*144 + sl
    int b = blk / K144, sl = blk - b * K144;
    int o = threadIdx.x;             // 32
    {
        size_t base = ((size_t)(b*32 + o))*4*K144 + sl;
        float2 a = g_C1P[base], bb = g_C1P[base + K144];
        float2 c = g_C1P[base + 2*K144], d = g_C1P[base + 3*K144];
        cin[o] = make_float2(a.x+bb.x+c.x+d.x, a.y+bb.y+c.y+d.y);
    }
    __syncwarp();
    const float* wrp = wr + (size_t)sl * 1024 + o;
    const float* wip = wi + (size_t)sl * 1024 + o;
    float ar = 0.f, ai = 0.f;
    #pragma unroll
    for (int i = 0; i < 32; i++) {
        float2 c = cin[i];
        float a = wrp[i*32], bb = wip[i*32];
        ar += c.x*a - c.y*bb;
        ai += c.x*bb + c.y*a;
    }
    const float invn = 1.0f / 262144.0f;
    c2s[o] = make_float2(ar*invn, ai*invn);
    __syncwarp();
    if (o < HID) {
        int j = o;
        float br = 0.f, bi = 0.f;
        #pragma unroll
        for (int q = 0; q < 32; q++) {
            float ax = w1r[j*32+q], ay = w1i[j*32+q];
            float2 c = c2s[q];
            br += ax*c.x - ay*c.y;
            bi += ax*c.y + ay*c.x;
        }
        g_C3[((size_t)(b*HID + j))*K144 + sl] = make_float2(br, bi);
    }
}

// ---------------- K67: inverse basis + inverse x-DFT + inverse y-DFT (packed) ----------------
__global__ void k67_inv() {
    __shared__ ull c3[K144];
    __shared__ ull twiA[1024];       // (c, s)
    __shared__ ull twiB[1024];       // (-s, c)
    __shared__ float2 S[256];
    int bj = blockIdx.x >> 4;        // b*16 + j
    int xch = blockIdx.x & 15;
    int b = bj >> 4, j = bj & 15;
    int t = threadIdx.x;             // 256
    if (t < K144) {
        float2 v = g_C3[(size_t)bj*K144 + t];
        c3[t] = pk(v.x, v.y);
    }
    for (int i = t; i < 1024; i += 256) {
        int k = i >> 6, jj = i & 63;
        int fk = k < 8 ? k : k - 16;
        float2 w = g_TW[(jj * fk) & 63];
        twiA[i] = pk(w.x, w.y);
        twiB[i] = pk(-w.y, w.x);
    }
    __syncthreads();
    // inverse basis: xs2[kx] for t = ky*16+kz
    ull xs2[16];
    #pragma unroll
    for (int kx = 0; kx < 16; kx++) {
        int m = (kx << 8) | t;
        int s = g_shell[m];
        const float* yw = &g_YW[m*9];
        ull acc = 0;
        #pragma unroll
        for (int l = 0; l < 9; l++) acc = ffma2(splat(yw[l]), c3[s*9 + l], acc);
        xs2[kx] = acc;
    }
    for (int xi = 0; xi < 4; xi++) {
        int xx = xch * 4 + xi;
        ull o = 0;
        #pragma unroll
        for (int kx = 0; kx < 16; kx++) {
            float2 v = upk(xs2[kx]);
            o = ffma2(splat(v.x), twiA[kx*64 + xx], o);
            o = ffma2(splat(v.y), twiB[kx*64 + xx], o);
        }
        S[t] = upk(o);
        __syncthreads();
        {
            int y = t & 63, kzg = t >> 6;
            ull acc[4] = {0, 0, 0, 0};
            for (int ky = 0; ky < 16; ky++) {
                ull wA = twiA[ky*64 + y], wB = twiB[ky*64 + y];
                #pragma unroll
                for (int i = 0; i < 4; i++) {
                    float2 v = S[ky*16 + kzg*4 + i];
                    acc[i] = ffma2(splat(v.x), wA, acc[i]);
                    acc[i] = ffma2(splat(v.y), wB, acc[i]);
                }
            }
            size_t base = (((size_t)b*64 + xx)*64 + y)*256 + j*16 + kzg*4;
            #pragma unroll
            for (int i = 0; i < 4; i++) g_T2[base + i] = upk(acc[i]);
        }
        __syncthreads();
    }
}

// ---------------- K8: fused epilogue, register-tiled + packed ----------------
__device__ __forceinline__ float gelu_t(float v) {
    float u = 0.7978845608028654f * (v + 0.044715f * v * v * v);
    return 0.5f * v * (1.0f + tanhf(u));
}

#define K8_SMEM 90496

__global__ void __launch_bounds__(256, 2)
k8_final(const float* __restrict__ x,
         const float* __restrict__ wgr,
         const float* __restrict__ w2r, const float* __restrict__ w2i,
         const float* __restrict__ b2r,
         float* __restrict__ out) {
    extern __shared__ char sm[];
    float*  s_x   = (float*)sm;                 // [4][32][64]   32KB
    float2* s_t2T = (float2*)(sm + 32768);      // [4][16kz][16j] 8KB
    float*  s_twc = (float*)(sm + 40960);       // [16][64]      4KB
    float*  s_tws = (float*)(sm + 45056);       // [16][64]      4KB
    float*  s_hr  = (float*)(sm + 49152);       // [4][16][64]  16KB
    float*  s_hi  = (float*)(sm + 65536);       // 16KB
    float2* s_wcT = (float2*)(sm + 81920);      // [32c][16j]    4KB
    float2* s_w2T = (float2*)(sm + 86016);      // [16j][32o] (w2r,-w2i) 4KB
    float2* s_bc  = (float2*)(sm + 90112);
    float*  s_b2  = (float*)(sm + 90240);
    float*  s_wg  = (float*)(sm + 90368);

    int blk = blockIdx.x;
    int b  = blk >> 10;
    int xc = (blk >> 4) & 63;
    int y0 = (blk & 15) * 4;
    int t = threadIdx.x;

    // stage x (float4)
    for (int i = t; i < 2048; i += 256) {
        int line = i >> 9, c = (i >> 4) & 31, zq = i & 15;
        float4 v = *(const float4*)&x[(((size_t)(b*32+c))*64 + xc)*4096 + (size_t)(y0+line)*64 + zq*4];
        *(float4*)&s_x[(line*32+c)*64 + zq*4] = v;
    }
    // stage t2, transposed to [kz][j]
    for (int i = t; i < 1024; i += 256) {
        int line = i >> 8, q = i & 255;
        int j = q >> 4, kz = q & 15;
        s_t2T[line*256 + kz*16 + j] =
            g_T2[((((size_t)b*64 + xc)*64) + (y0+line))*256 + q];
    }
    // twiddles e^{+i}
    for (int i = t; i < 1024; i += 256) {
        int kz = i >> 6, z = i & 63;
        int fk = kz < 8 ? kz : kz - 16;
        float2 w = g_TW[(z*fk) & 63];
        s_twc[i] = w.x;
        s_tws[i] = w.y;
    }
    for (int i = t; i < 512; i += 256) {
        int j = i & 15, c = i >> 4;
        s_wcT[c*16 + j] = g_WC[j*32 + c];
        int jj = i >> 5, o = i & 31;
        s_w2T[jj*32 + o] = make_float2(w2r[o*16 + jj], -w2i[o*16 + jj]);
    }
    if (t < 32) {
        s_b2[t] = b2r[t];
        s_wg[t] = wgr[t];
        if (t < 16) s_bc[t] = g_BC[t];
    }
    __syncthreads();

    int line = t >> 6, sub = t & 63;
    int jg = sub >> 4, zg = sub & 15;
    int z0 = zg * 4;
    const float* xl = &s_x[line*2048];

    // ---- pass 1: g = ifft_z(t2) + Wc*x + bc ; h = cgelu(g) ----
    {
        ull accR[4][2], accI[4][2];
        #pragma unroll
        for (int p = 0; p < 4; p++) {
            float2 bc = s_bc[jg*4 + p];
            accR[p][0] = accR[p][1] = splat(bc.x);
            accI[p][0] = accI[p][1] = splat(bc.y);
        }
        const float2* t2p = &s_t2T[line*256];
        #pragma unroll
        for (int kz = 0; kz < 16; kz++) {
            float4 ta = *(const float4*)&t2p[kz*16 + jg*4];
            float4 tb = *(const float4*)&t2p[kz*16 + jg*4 + 2];
            float4 c4 = *(const float4*)&s_twc[kz*64 + z0];
            float4 s4 = *(const float4*)&s_tws[kz*64 + z0];
            ull wc0 = pk(c4.x, c4.y), wc1 = pk(c4.z, c4.w);
            ull ws0 = pk(s4.x, s4.y), ws1 = pk(s4.z, s4.w);
            float vx[4] = {ta.x, ta.z, tb.x, tb.z};
            float vy[4] = {ta.y, ta.w, tb.y, tb.w};
            #pragma unroll
            for (int p = 0; p < 4; p++) {
                ull sx = splat(vx[p]), sy = splat(vy[p]), syn = splat(-vy[p]);
                accR[p][0] = ffma2(sx, wc0, accR[p][0]);
                accR[p][0] = ffma2(syn, ws0, accR[p][0]);
                accR[p][1] = ffma2(sx, wc1, accR[p][1]);
                accR[p][1] = ffma2(syn, ws1, accR[p][1]);
                accI[p][0] = ffma2(sx, ws0, accI[p][0]);
                accI[p][0] = ffma2(sy, wc0, accI[p][0]);
                accI[p][1] = ffma2(sx, ws1, accI[p][1]);
                accI[p][1] = ffma2(sy, wc1, accI[p][1]);
            }
        }
        #pragma unroll 4
        for (int c = 0; c < 32; c++) {
            float4 xv = *(const float4*)&xl[c*64 + z0];
            ull x01 = pk(xv.x, xv.y), x23 = pk(xv.z, xv.w);
            float4 wa = *(const float4*)&s_wcT[c*16 + jg*4];
            float4 wb = *(const float4*)&s_wcT[c*16 + jg*4 + 2];
            float wr[4] = {wa.x, wa.z, wb.x, wb.z};
            float wi[4] = {wa.y, wa.w, wb.y, wb.w};
            #pragma unroll
            for (int p = 0; p < 4; p++) {
                ull sr = splat(wr[p]), si = splat(wi[p]);
                accR[p][0] = ffma2(sr, x01, accR[p][0]);
                accR[p][1] = ffma2(sr, x23, accR[p][1]);
                accI[p][0] = ffma2(si, x01, accI[p][0]);
                accI[p][1] = ffma2(si, x23, accI[p][1]);
            }
        }
        #pragma unroll
        for (int p = 0; p < 4; p++) {
            int j = jg*4 + p;
            float2 r0 = upk(accR[p][0]), r1 = upk(accR[p][1]);
            float2 i0 = upk(accI[p][0]), i1 = upk(accI[p][1]);
            *(float2*)&s_hr[(line*16+j)*64 + z0]     = make_float2(gelu_t(r0.x), gelu_t(r0.y));
            *(float2*)&s_hr[(line*16+j)*64 + z0 + 2] = make_float2(gelu_t(r1.x), gelu_t(r1.y));
            *(float2*)&s_hi[(line*16+j)*64 + z0]     = make_float2(gelu_t(i0.x), gelu_t(i0.y));
            *(float2*)&s_hi[(line*16+j)*64 + z0 + 2] = make_float2(gelu_t(i1.x), gelu_t(i1.y));
        }
    }
    __syncthreads();

    // ---- pass 2: out = Re(W2 h) + b2 + x*wg ----
    {
        int og = jg;                 // 4 groups of 8 outputs
        ull acc[8][2];
        #pragma unroll
        for (int q = 0; q < 8; q++) { acc[q][0] = 0; acc[q][1] = 0; }
        const float* hrl = &s_hr[line*1024];
        const float* hil = &s_hi[line*1024];
        #pragma unroll
        for (int j = 0; j < 16; j++) {
            float4 hr4 = *(const float4*)&hrl[j*64 + z0];
            float4 hi4 = *(const float4*)&hil[j*64 + z0];
            ull hr01 = pk(hr4.x, hr4.y), hr23 = pk(hr4.z, hr4.w);
            ull hi01 = pk(hi4.x, hi4.y), hi23 = pk(hi4.z, hi4.w);
            const float2* w2p = &s_w2T[j*32 + og*8];
            #pragma unroll
            for (int qq = 0; qq < 8; qq += 2) {
                float4 w4 = *(const float4*)&w2p[qq];
                ull a0 = splat(w4.x), b0 = splat(w4.y);
                ull a1 = splat(w4.z), b1 = splat(w4.w);
                acc[qq][0]   = ffma2(a0, hr01, acc[qq][0]);
                acc[qq][0]   = ffma2(b0, hi01, acc[qq][0]);
                acc[qq][1]   = ffma2(a0, hr23, acc[qq][1]);
                acc[qq][1]   = ffma2(b0, hi23, acc[qq][1]);
                acc[qq+1][0] = ffma2(a1, hr01, acc[qq+1][0]);
                acc[qq+1][0] = ffma2(b1, hi01, acc[qq+1][0]);
                acc[qq+1][1] = ffma2(a1, hr23, acc[qq+1][1]);
                acc[qq+1][1] = ffma2(b1, hi23, acc[qq+1][1]);
            }
        }
        int y = y0 + line;
        #pragma unroll
        for (int q = 0; q < 8; q++) {
            int o = og*8 + q;
            float4 xv = *(const float4*)&xl[o*64 + z0];
            float2 a0 = upk(acc[q][0]), a1 = upk(acc[q][1]);
            float bb = s_b2[o], g = s_wg[o];
            float4 r;
            r.x = a0.x + bb + xv.x*g;
            r.y = a0.y + bb + xv.y*g;
            r.z = a1.x + bb + xv.z*g;
            r.w = a1.y + bb + xv.w*g;
            *(float4*)&out[(((size_t)(b*32+o))*64 + xc)*4096 + (size_t)y*64 + z0] = r;
        }
    }
}

// ---------------- launch ----------------
extern "C" void kernel_launch(void* const* d_in, const int* in_sizes, int n_in,
                              void* d_out, int out_size) {
    const float* x    = (const float*)d_in[0];
    const float* wfr  = (const float*)d_in[1];
    const float* wfi  = (const float*)d_in[2];
    const float* bfr  = (const float*)d_in[3];
    const float* bfi  = (const float*)d_in[4];
    const float* wgr  = (const float*)d_in[5];
    const float* wsr  = (const float*)d_in[7];
    const float* wsi  = (const float*)d_in[8];
    const float* w1r  = (const float*)d_in[9];
    const float* w1i  = (const float*)d_in[10];
    const float* b1r  = (const float*)d_in[11];
    const float* b1i  = (const float*)d_in[12];
    const float* w2r  = (const float*)d_in[13];
    const float* w2i  = (const float*)d_in[14];
    const float* b2r  = (const float*)d_in[15];
    float* out = (float*)d_out;

    cudaFuncSetAttribute(k8_final, cudaFuncAttributeMaxDynamicSharedMemorySize, K8_SMEM);

    k0_init<<<1, 512>>>();
    kpre<<<1, 512>>>(wfr, wfi, bfr, bfi, w1r, w1i, b1r, b1i);
    k12_fwd<<<BB*CC*64, 256>>>(x);
    k3_xdft<<<BB*CC*4, 256>>>();
    k4_proj<<<BB*CC*4, 256>>>();
    k5_conv<<<BB*K144, 32>>>(wsr, wsi, w1r, w1i);
    k67_inv<<<BB*HID*16, 256>>>();
    k8_final<<<BB*64*16, 256, K8_SMEM>>>(x, wgr, w2r, w2i, b2r, out);
}